// round 17
// baseline (speedup 1.0000x reference)
#include <cuda_runtime.h>
#include <cuda_fp16.h>
#include <math.h>
#include <stdint.h>

// ---------------------------------------------------------------------------
// EncoderLayer: B=4, S=2048, FEAT=1024, HEADS=16, HDIM=64, FF=500.
// Round 15: V-transpose fused into QKV epilogue; batched weight transposes.
// fp16 mma.m16n8k16 + ldmatrix.x4 everywhere, fp32 accum.
// Faithful: masked fill -1e-9, std ddof=1, ELU.
// ---------------------------------------------------------------------------
namespace {
constexpr int kFeat  = 1024;
constexpr int kHeads = 16;
constexpr int kHdim  = 64;
constexpr int kFF    = 500;
constexpr int kFFp   = 512;
constexpr int kB     = 4;
constexpr int kS     = 2048;
constexpr int kRows  = kB * kS;
constexpr int kQKV   = 3 * kFeat;      // 3072
constexpr float kEps = 1e-6f;
constexpr int kWork  = (kS / 128) * kHeads * kB;   // 1024 flash work items
}

__device__ __half g_x2  [kRows * kFeat];
__device__ __half g_qkvh[kRows * kQKV];             // q,k used; v cols unused
__device__ __half g_vT  [kB * kHeads * kHdim * kS]; // V^T per (b,h): [d][s]
__device__ __half g_attn[kRows * kFeat];
__device__ float  g_xres[kRows * kFeat];
__device__ __half g_h   [kRows * kFFp];
__device__ __half g_WqkvT[kQKV * kFeat];
__device__ float  g_bqkv [kQKV];
__device__ __half g_WoT [kFeat * kFeat];
__device__ __half g_W1T [kFFp * kFeat];
__device__ float  g_b1p [kFFp];
__device__ __half g_W2T [kFeat * kFFp];
__device__ unsigned g_mbits[kB * kS * (kS / 32)];

__device__ __forceinline__ void ldm_x4(uint32_t& r0, uint32_t& r1,
                                       uint32_t& r2, uint32_t& r3, uint32_t a) {
    asm volatile("ldmatrix.sync.aligned.m8n8.x4.shared.b16 {%0,%1,%2,%3}, [%4];"
                 : "=r"(r0), "=r"(r1), "=r"(r2), "=r"(r3) : "r"(a));
}

// ---------------------------------------------------------------------------
// Prep: bias concat/pad + mask bit packing.
// ---------------------------------------------------------------------------
__global__ __launch_bounds__(256)
void prep_kernel(const float* __restrict__ bq, const float* __restrict__ bk,
                 const float* __restrict__ bv, const float* __restrict__ b1,
                 const int* __restrict__ mask) {
    const int idx = blockIdx.x * 256 + threadIdx.x;
    if (idx < kFeat) {
        g_bqkv[idx] = bq[idx];
        g_bqkv[kFeat + idx] = bk[idx];
        g_bqkv[2 * kFeat + idx] = bv[idx];
    }
    if (idx < kFFp) g_b1p[idx] = (idx < kFF) ? b1[idx] : 0.f;
    if (idx < kB * kS * (kS / 32)) {
        const int w = idx % (kS / 32);
        const int bq_ = idx / (kS / 32);
        const int* mr = mask + (long long)bq_ * kS + w * 32;
        unsigned bits = 0;
        #pragma unroll
        for (int j = 0; j < 32; ++j)
            if (mr[j] != 0) bits |= (1u << j);
        g_mbits[idx] = bits;
    }
}

// Batched transpose of ALL six weights -> half [n][k] (zero-padded FF dims).
// z: 0=Wq,1=Wk,2=Wv (thirds of WqkvT), 3=Wo, 4=W1, 5=W2. Block 32x8, grid 32x32x6.
__global__ void transpose_all(const float* __restrict__ Wq,
                              const float* __restrict__ Wk,
                              const float* __restrict__ Wv,
                              const float* __restrict__ Wo,
                              const float* __restrict__ W1,
                              const float* __restrict__ W2) {
    __shared__ float tile[32][33];
    const int z = blockIdx.z;
    const float* in;
    __half* out;
    int R, C, Rp, Cp;
    if (z < 4) {
        in = (z == 0) ? Wq : (z == 1) ? Wk : (z == 2) ? Wv : Wo;
        out = (z == 3) ? g_WoT : (g_WqkvT + (size_t)z * kFeat * kFeat);
        R = C = Rp = Cp = kFeat;
    } else if (z == 4) {
        if (blockIdx.x >= 16) return;               // C=500 -> 16 col-blocks
        in = W1; out = g_W1T; R = kFeat; C = kFF; Rp = kFeat; Cp = kFFp;
    } else {
        if (blockIdx.y >= 16) return;               // R=500 -> 16 row-blocks
        in = W2; out = g_W2T; R = kFF; C = kFeat; Rp = kFFp; Cp = kFeat;
    }
    const int c0 = blockIdx.x * 32, r0 = blockIdx.y * 32;
    const int x = threadIdx.x, y = threadIdx.y;
    #pragma unroll
    for (int j = 0; j < 32; j += 8) {
        const int r = r0 + y + j, c = c0 + x;
        tile[y + j][x] = (r < R && c < C) ? in[(size_t)r * C + c] : 0.f;
    }
    __syncthreads();
    #pragma unroll
    for (int j = 0; j < 32; j += 8) {
        const int oc = c0 + y + j, orr = r0 + x;
        if (oc < Cp && orr < Rp)
            out[(size_t)oc * Rp + orr] = __float2half(tile[x][y + j]);
    }
}

// ---------------------------------------------------------------------------
// LayerNorm (ddof=1), output half.
// ---------------------------------------------------------------------------
__global__ __launch_bounds__(256)
void ln_kernel(const float* __restrict__ x,
               const float* __restrict__ alpha,
               const float* __restrict__ bias,
               __half* __restrict__ out) {
    const int row = blockIdx.x;
    const float4* xr = (const float4*)(x + (size_t)row * kFeat);
    __half2* orow = (__half2*)(out + (size_t)row * kFeat);

    float4 vals = xr[threadIdx.x];
    float s  = vals.x + vals.y + vals.z + vals.w;
    float s2 = vals.x*vals.x + vals.y*vals.y + vals.z*vals.z + vals.w*vals.w;
    #pragma unroll
    for (int o = 16; o; o >>= 1) {
        s  += __shfl_xor_sync(0xFFFFFFFFu, s,  o);
        s2 += __shfl_xor_sync(0xFFFFFFFFu, s2, o);
    }
    __shared__ float shs[8], shs2[8];
    const int wid = threadIdx.x >> 5, lid = threadIdx.x & 31;
    if (lid == 0) { shs[wid] = s; shs2[wid] = s2; }
    __syncthreads();
    if (wid == 0) {
        s  = (lid < 8) ? shs[lid]  : 0.f;
        s2 = (lid < 8) ? shs2[lid] : 0.f;
        #pragma unroll
        for (int o = 4; o; o >>= 1) {
            s  += __shfl_xor_sync(0xFFFFFFFFu, s,  o);
            s2 += __shfl_xor_sync(0xFFFFFFFFu, s2, o);
        }
        if (lid == 0) { shs[0] = s; shs2[0] = s2; }
    }
    __syncthreads();
    s = shs[0]; s2 = shs2[0];

    const float mean = s / (float)kFeat;
    const float var  = fmaxf(0.f, (s2 - s * mean) / (float)(kFeat - 1));
    const float inv  = 1.f / (sqrtf(var) + kEps);

    const float4 a4 = ((const float4*)alpha)[threadIdx.x];
    const float4 b4 = ((const float4*)bias)[threadIdx.x];
    orow[2 * threadIdx.x] = __floats2half2_rn(
        a4.x * (vals.x - mean) * inv + b4.x,
        a4.y * (vals.y - mean) * inv + b4.y);
    orow[2 * threadIdx.x + 1] = __floats2half2_rn(
        a4.z * (vals.z - mean) * inv + b4.z,
        a4.w * (vals.w - mean) * inv + b4.w);
}

// ---------------------------------------------------------------------------
// fp16 dense GEMM (mma.m16n8k16 + ldmatrix.x4). Tile 128x256, BK=64,
// 3-stage cp.async, 8 warps as 2(m)x4(n), warp tile 64x64.
// VOUT: cols >= 2048 write transposed into g_vT (QKV kernel only).
// ---------------------------------------------------------------------------
template <int KDIM, int SCM, int EPI, int SCALEQ, int OUTH, int VOUT>
__global__ __launch_bounds__(256)
void gemm_fp16(const __half* __restrict__ A, const __half* __restrict__ Bt,
               const float* __restrict__ bias, const float* __restrict__ resid,
               void* __restrict__ Cv) {
    constexpr int nk = KDIM / 64;
    constexpr int ASTR = 72, ASZ = 128 * ASTR;
    constexpr int BSTR = 72, BSZ = 256 * BSTR;

    extern __shared__ __half hsm[];
    __half* AsS[3]; __half* BsS[3];
    #pragma unroll
    for (int s = 0; s < 3; ++s) {
        AsS[s] = hsm + s * (ASZ + BSZ);
        BsS[s] = AsS[s] + ASZ;
    }

    const int tid = threadIdx.x;
    const int w = tid >> 5, l = tid & 31;
    const int wm = w & 1, wn = w >> 1;
    const int lr = l >> 2, lc = l & 3;
    const int m0 = blockIdx.y * 128, n0 = blockIdx.x * 256;

    const uint32_t aOff = ((uint32_t)((wm * 64 + (l & 7) + ((l >> 3) & 1) * 8) * ASTR
                                      + (l >> 4) * 8)) * 2;
    const uint32_t bOff = ((uint32_t)((wn * 64 + (l & 7) + (l >> 4) * 8) * BSTR
                                      + ((l >> 3) & 1) * 8)) * 2;

    auto issue = [&](int t) {
        if (t >= nk) return;
        __half* as = AsS[t % 3];
        __half* bs = BsS[t % 3];
        const int k0 = t * 64;
        #pragma unroll
        for (int p = 0; p < 4; ++p) {
            const int idx = tid + p * 256;
            const int r = idx >> 3, c16 = idx & 7;
            const uint32_t d = (uint32_t)__cvta_generic_to_shared(as + r * ASTR + c16 * 8);
            const __half* sp = A + (size_t)(m0 + r) * KDIM + k0 + c16 * 8;
            asm volatile("cp.async.ca.shared.global [%0], [%1], 16;" :: "r"(d), "l"(sp));
        }
        #pragma unroll
        for (int p = 0; p < 8; ++p) {
            const int idx = tid + p * 256;
            const int r = idx >> 3, c16 = idx & 7;
            const uint32_t d = (uint32_t)__cvta_generic_to_shared(bs + r * BSTR + c16 * 8);
            const __half* sp = Bt + (size_t)(n0 + r) * KDIM + k0 + c16 * 8;
            asm volatile("cp.async.ca.shared.global [%0], [%1], 16;" :: "r"(d), "l"(sp));
        }
    };

    issue(0); asm volatile("cp.async.commit_group;" ::: "memory");
    issue(1); asm volatile("cp.async.commit_group;" ::: "memory");

    float acc[4][8][4];
    #pragma unroll
    for (int i = 0; i < 4; ++i)
        #pragma unroll
        for (int j = 0; j < 8; ++j)
            #pragma unroll
            for (int c = 0; c < 4; ++c) acc[i][j][c] = 0.f;

    for (int t = 0; t < nk; ++t) {
        asm volatile("cp.async.wait_group 1;" ::: "memory");
        __syncthreads();
        const uint32_t aB = (uint32_t)__cvta_generic_to_shared(AsS[t % 3]) + aOff;
        const uint32_t bB = (uint32_t)__cvta_generic_to_shared(BsS[t % 3]) + bOff;
        #pragma unroll
        for (int k0 = 0; k0 < 64; k0 += 16) {
            uint32_t af[4][4], bf[4][4];
            #pragma unroll
            for (int mt = 0; mt < 4; ++mt)
                ldm_x4(af[mt][0], af[mt][1], af[mt][2], af[mt][3],
                       aB + (uint32_t)((mt * 16 * ASTR + k0) * 2));
            #pragma unroll
            for (int p = 0; p < 4; ++p)
                ldm_x4(bf[p][0], bf[p][1], bf[p][2], bf[p][3],
                       bB + (uint32_t)((p * 16 * BSTR + k0) * 2));
            #pragma unroll
            for (int p = 0; p < 4; ++p) {
                #pragma unroll
                for (int mt = 0; mt < 4; ++mt) {
                    asm volatile(
                        "mma.sync.aligned.m16n8k16.row.col.f32.f16.f16.f32 "
                        "{%0,%1,%2,%3}, {%4,%5,%6,%7}, {%8,%9}, {%0,%1,%2,%3};"
                        : "+f"(acc[mt][2 * p][0]), "+f"(acc[mt][2 * p][1]),
                          "+f"(acc[mt][2 * p][2]), "+f"(acc[mt][2 * p][3])
                        : "r"(af[mt][0]), "r"(af[mt][1]),
                          "r"(af[mt][2]), "r"(af[mt][3]),
                          "r"(bf[p][0]), "r"(bf[p][1]));
                    asm volatile(
                        "mma.sync.aligned.m16n8k16.row.col.f32.f16.f16.f32 "
                        "{%0,%1,%2,%3}, {%4,%5,%6,%7}, {%8,%9}, {%0,%1,%2,%3};"
                        : "+f"(acc[mt][2 * p + 1][0]), "+f"(acc[mt][2 * p + 1][1]),
                          "+f"(acc[mt][2 * p + 1][2]), "+f"(acc[mt][2 * p + 1][3])
                        : "r"(af[mt][0]), "r"(af[mt][1]),
                          "r"(af[mt][2]), "r"(af[mt][3]),
                          "r"(bf[p][2]), "r"(bf[p][3]));
                }
            }
        }
        issue(t + 2);
        asm volatile("cp.async.commit_group;" ::: "memory");
    }

    float* Cf = (float*)Cv;
    __half* Ch = (__half*)Cv;
    #pragma unroll
    for (int mt = 0; mt < 4; ++mt) {
        #pragma unroll
        for (int nt = 0; nt < 8; ++nt) {
            const int r0 = m0 + wm * 64 + mt * 16 + lr;
            const int c  = n0 + wn * 64 + nt * 8 + lc * 2;
            const float bx = bias[c], by = bias[c + 1];
            const float sc = (SCALEQ && c < 1024) ? 0.125f : 1.0f;
            #pragma unroll
            for (int hh = 0; hh < 2; ++hh) {
                const int r = r0 + hh * 8;
                float v0 = (acc[mt][nt][hh * 2 + 0] + bx) * sc;
                float v1 = (acc[mt][nt][hh * 2 + 1] + by) * sc;
                if (EPI == 1) {
                    v0 = (v0 > 0.f) ? v0 : expm1f(v0);
                    v1 = (v1 > 0.f) ? v1 : expm1f(v1);
                }
                if (VOUT && c >= 2048) {
                    // v columns: write transposed into g_vT[(b,h)][d][s]
                    const int b_ = r >> 11, s_ = r & (kS - 1);
                    const int hd = c - 2048;
                    __half* vb = g_vT + (((size_t)(b_ * kHeads + (hd >> 6)) * kHdim
                                          + (hd & 63)) * kS) + s_;
                    vb[0]  = __float2half(v0);
                    vb[kS] = __float2half(v1);
                } else {
                    const size_t ci = (size_t)r * SCM + c;
                    if (resid) {
                        const float2 rr = *(const float2*)&resid[ci];
                        v0 += rr.x; v1 += rr.y;
                    }
                    if (OUTH) {
                        *(__half2*)&Ch[ci] = __floats2half2_rn(v0, v1);
                    } else {
                        float2 o; o.x = v0; o.y = v1;
                        *(float2*)&Cf[ci] = o;
                    }
                }
            }
        }
    }
}

// ---------------------------------------------------------------------------
// Flash attention: persistent, fp16 m16n8k16 + ldmatrix.x4 fragments.
// Bq=128, Bk=64, 8 warps as 4(m)x2(n), warp tile 32x32, 2 CTAs/SM.
// No-max softmax (masked exp == 1.0f exactly).
// ---------------------------------------------------------------------------
namespace fl {
constexpr int STR = 72;
constexpr int QO  = 0;
constexpr int KO  = QO + 128 * STR;
constexpr int VO  = KO + 64 * STR;
constexpr int PO  = VO + 64 * STR;
constexpr int MO  = PO + 128 * STR;
constexpr int RSO = MO + 512;
constexpr int TOT = RSO + 512;
}

__global__ __launch_bounds__(256, 2)
void flash_kernel(const __half* __restrict__ qkv, const __half* __restrict__ vT,
                  __half* __restrict__ attn) {
    extern __shared__ __half hs[];
    __half* sQ = hs + fl::QO;
    __half* sK = hs + fl::KO;
    __half* sVt = hs + fl::VO;
    __half* sP = hs + fl::PO;
    unsigned* sM = (unsigned*)(hs + fl::MO);
    float* sRS = (float*)(hs + fl::RSO);

    const int tid = threadIdx.x;
    const int w = tid >> 5, l = tid & 31;
    const int wm = w & 3, wn = w >> 2;
    const int lr = l >> 2, lc = l & 3;
    constexpr int nT = kS / 64;

    const uint32_t aLane = ((uint32_t)(((l & 7) + ((l >> 3) & 1) * 8) * fl::STR
                                       + (l >> 4) * 8)) * 2;
    const uint32_t bLane = ((uint32_t)(((l & 7) + (l >> 4) * 8) * fl::STR
                                       + ((l >> 3) & 1) * 8)) * 2;
    const uint32_t qB0 = (uint32_t)__cvta_generic_to_shared(sQ) + aLane
                       + (uint32_t)(wm * 32 * fl::STR * 2);
    const uint32_t pB0 = (uint32_t)__cvta_generic_to_shared(sP) + aLane
                       + (uint32_t)(wm * 32 * fl::STR * 2);
    const uint32_t kB0 = (uint32_t)__cvta_generic_to_shared(sK) + bLane
                       + (uint32_t)(wn * 32 * fl::STR * 2);
    const uint32_t vB0 = (uint32_t)__cvta_generic_to_shared(sVt) + bLane
                       + (uint32_t)(wn * 32 * fl::STR * 2);

    for (int work = blockIdx.x; work < kWork; work += gridDim.x) {
        const int qt = work & 15;
        const int h = (work >> 4) & 15;
        const int b = work >> 8;
        const int q0 = qt * 128;

        const __half* qg = qkv + ((size_t)(b * kS + q0)) * kQKV + h * kHdim;
        const __half* kg = qkv + ((size_t)b * kS) * kQKV + kFeat + h * kHdim;
        const __half* vg = vT + (size_t)(b * kHeads + h) * kHdim * kS;
        const unsigned* mg = g_mbits + ((size_t)b * kS + q0) * (kS / 32);

        auto loadQ = [&]() {
            #pragma unroll
            for (int p = 0; p < 4; ++p) {
                const int idx = tid + p * 256;
                const int r = idx >> 3, c16 = idx & 7;
                const uint32_t d = (uint32_t)__cvta_generic_to_shared(sQ + r * fl::STR + c16 * 8);
                const __half* sp = qg + (size_t)r * kQKV + c16 * 8;
                asm volatile("cp.async.ca.shared.global [%0], [%1], 16;" :: "r"(d), "l"(sp));
            }
        };
        auto loadKM = [&](int kt) {
            #pragma unroll
            for (int p = 0; p < 2; ++p) {
                const int idx = tid + p * 256;
                const int r = idx >> 3, c16 = idx & 7;
                const uint32_t d = (uint32_t)__cvta_generic_to_shared(sK + r * fl::STR + c16 * 8);
                const __half* sp = kg + ((size_t)(kt * 64 + r)) * kQKV + c16 * 8;
                asm volatile("cp.async.ca.shared.global [%0], [%1], 16;" :: "r"(d), "l"(sp));
            }
            {
                const int r = tid >> 1, ww = tid & 1;
                const uint32_t d = (uint32_t)__cvta_generic_to_shared(sM + r * 2 + ww);
                const unsigned* sp = mg + (size_t)r * (kS / 32) + kt * 2 + ww;
                asm volatile("cp.async.ca.shared.global [%0], [%1], 4;" :: "r"(d), "l"(sp));
            }
        };
        auto loadV = [&](int kt) {
            #pragma unroll
            for (int p = 0; p < 2; ++p) {
                const int idx = tid + p * 256;
                const int r = idx >> 3, c16 = idx & 7;
                const uint32_t d = (uint32_t)__cvta_generic_to_shared(sVt + r * fl::STR + c16 * 8);
                const __half* sp = vg + (size_t)r * kS + kt * 64 + c16 * 8;
                asm volatile("cp.async.ca.shared.global [%0], [%1], 16;" :: "r"(d), "l"(sp));
            }
        };

        loadQ(); loadKM(0);
        asm volatile("cp.async.commit_group;" ::: "memory");
        loadV(0);
        asm volatile("cp.async.commit_group;" ::: "memory");

        float lOld[4];
        #pragma unroll
        for (int i = 0; i < 4; ++i) lOld[i] = 0.f;
        float accO[2][4][4];
        #pragma unroll
        for (int i = 0; i < 2; ++i)
            #pragma unroll
            for (int j = 0; j < 4; ++j)
                #pragma unroll
                for (int c = 0; c < 4; ++c) accO[i][j][c] = 0.f;

        for (int kt = 0; kt < nT; ++kt) {
            asm volatile("cp.async.wait_group 1;" ::: "memory");
            __syncthreads();

            // ---- S = Q @ K^T ----
            float accS[2][4][4];
            #pragma unroll
            for (int i = 0; i < 2; ++i)
                #pragma unroll
                for (int j = 0; j < 4; ++j)
                    #pragma unroll
                    for (int c = 0; c < 4; ++c) accS[i][j][c] = 0.f;
            #pragma unroll
            for (int k0 = 0; k0 < 64; k0 += 16) {
                uint32_t af[2][4], bf[2][4];
                #pragma unroll
                for (int mt = 0; mt < 2; ++mt)
                    ldm_x4(af[mt][0], af[mt][1], af[mt][2], af[mt][3],
                           qB0 + (uint32_t)((mt * 16 * fl::STR + k0) * 2));
                #pragma unroll
                for (int p = 0; p < 2; ++p)
                    ldm_x4(bf[p][0], bf[p][1], bf[p][2], bf[p][3],
                           kB0 + (uint32_t)((p * 16 * fl::STR + k0) * 2));
                #pragma unroll
                for (int p = 0; p < 2; ++p) {
                    #pragma unroll
                    for (int mt = 0; mt < 2; ++mt) {
                        asm volatile(
                            "mma.sync.aligned.m16n8k16.row.col.f32.f16.f16.f32 "
                            "{%0,%1,%2,%3}, {%4,%5,%6,%7}, {%8,%9}, {%0,%1,%2,%3};"
                            : "+f"(accS[mt][2 * p][0]), "+f"(accS[mt][2 * p][1]),
                              "+f"(accS[mt][2 * p][2]), "+f"(accS[mt][2 * p][3])
                            : "r"(af[mt][0]), "r"(af[mt][1]),
                              "r"(af[mt][2]), "r"(af[mt][3]),
                              "r"(bf[p][0]), "r"(bf[p][1]));
                        asm volatile(
                            "mma.sync.aligned.m16n8k16.row.col.f32.f16.f16.f32 "
                            "{%0,%1,%2,%3}, {%4,%5,%6,%7}, {%8,%9}, {%0,%1,%2,%3};"
                            : "+f"(accS[mt][2 * p + 1][0]), "+f"(accS[mt][2 * p + 1][1]),
                              "+f"(accS[mt][2 * p + 1][2]), "+f"(accS[mt][2 * p + 1][3])
                            : "r"(af[mt][0]), "r"(af[mt][1]),
                              "r"(af[mt][2]), "r"(af[mt][3]),
                              "r"(bf[p][2]), "r"(bf[p][3]));
                    }
                }
            }

            // ---- p = mask ? exp(s) : 1.0f -> sP; per-lane l partials ----
            #pragma unroll
            for (int mt = 0; mt < 2; ++mt) {
                #pragma unroll
                for (int hh = 0; hh < 2; ++hh) {
                    const int rowL = wm * 32 + mt * 16 + hh * 8 + lr;
                    const unsigned mw = sM[rowL * 2 + wn];
                    float psum = 0.f;
                    #pragma unroll
                    for (int nt = 0; nt < 4; ++nt) {
                        const unsigned two = (mw >> (nt * 8 + 2 * lc)) & 3u;
                        float p0 = __expf(accS[mt][nt][hh * 2 + 0]);
                        float p1 = __expf(accS[mt][nt][hh * 2 + 1]);
                        if (!(two & 1u)) p0 = 1.0f;
                        if (!(two & 2u)) p1 = 1.0f;
                        psum += p0 + p1;
                        const int colb = wn * 32 + nt * 8 + 2 * lc;
                        *(__half2*)&sP[rowL * fl::STR + colb] = __floats2half2_rn(p0, p1);
                    }
                    lOld[mt * 2 + hh] += psum;
                }
            }

            asm volatile("cp.async.wait_group 0;" ::: "memory");
            __syncthreads();

            if (kt + 1 < nT) loadKM(kt + 1);
            asm volatile("cp.async.commit_group;" ::: "memory");

            // ---- O += P @ V ----
            #pragma unroll
            for (int k0 = 0; k0 < 64; k0 += 16) {
                uint32_t af[2][4], bf[2][4];
                #pragma unroll
                for (int mt = 0; mt < 2; ++mt)
                    ldm_x4(af[mt][0], af[mt][1], af[mt][2], af[mt][3],
                           pB0 + (uint32_t)((mt * 16 * fl::STR + k0) * 2));
                #pragma unroll
                for (int p = 0; p < 2; ++p)
                    ldm_x4(bf[p][0], bf[p][1], bf[p][2], bf[p][3],
                           vB0 + (uint32_t)((p * 16 * fl::STR + k0) * 2));
                #pragma unroll
                for (int p = 0; p < 2; ++p) {
                    #pragma unroll
                    for (int mt = 0; mt < 2; ++mt) {
                        asm volatile(
                            "mma.sync.aligned.m16n8k16.row.col.f32.f16.f16.f32 "
                            "{%0,%1,%2,%3}, {%4,%5,%6,%7}, {%8,%9}, {%0,%1,%2,%3};"
                            : "+f"(accO[mt][2 * p][0]), "+f"(accO[mt][2 * p][1]),
                              "+f"(accO[mt][2 * p][2]), "+f"(accO[mt][2 * p][3])
                            : "r"(af[mt][0]), "r"(af[mt][1]),
                              "r"(af[mt][2]), "r"(af[mt][3]),
                              "r"(bf[p][0]), "r"(bf[p][1]));
                        asm volatile(
                            "mma.sync.aligned.m16n8k16.row.col.f32.f16.f16.f32 "
                            "{%0,%1,%2,%3}, {%4,%5,%6,%7}, {%8,%9}, {%0,%1,%2,%3};"
                            : "+f"(accO[mt][2 * p + 1][0]), "+f"(accO[mt][2 * p + 1][1]),
                              "+f"(accO[mt][2 * p + 1][2]), "+f"(accO[mt][2 * p + 1][3])
                            : "r"(af[mt][0]), "r"(af[mt][1]),
                              "r"(af[mt][2]), "r"(af[mt][3]),
                              "r"(bf[p][2]), "r"(bf[p][3]));
                    }
                }
            }
            __syncthreads();

            if (kt + 1 < nT) loadV(kt + 1);
            asm volatile("cp.async.commit_group;" ::: "memory");
        }

        // ---- finalize ----
        #pragma unroll
        for (int mt = 0; mt < 2; ++mt)
            #pragma unroll
            for (int hh = 0; hh < 2; ++hh) {
                const int idx4 = mt * 2 + hh;
                const int rowL = wm * 32 + mt * 16 + hh * 8 + lr;
                float lv = lOld[idx4];
                lv += __shfl_xor_sync(0xFFFFFFFFu, lv, 1);
                lv += __shfl_xor_sync(0xFFFFFFFFu, lv, 2);
                if (lc == 0) sRS[wn * 128 + rowL] = lv;
            }
        __syncthreads();

        __half* ag = attn + ((size_t)(b * kS + q0)) * kFeat + h * kHdim;
        #pragma unroll
        for (int mt = 0; mt < 2; ++mt) {
            #pragma unroll
            for (int hh = 0; hh < 2; ++hh) {
                const int rowL = wm * 32 + mt * 16 + hh * 8 + lr;
                const float invl = 1.f / (sRS[rowL] + sRS[128 + rowL]);
                #pragma unroll
                for (int nt = 0; nt < 4; ++nt) {
                    const int col = wn * 32 + nt * 8 + 2 * lc;
                    *(__half2*)&ag[(size_t)rowL * kFeat + col] = __floats2half2_rn(
                        accO[mt][nt][hh * 2 + 0] * invl,
                        accO[mt][nt][hh * 2 + 1] * invl);
                }
            }
        }
        __syncthreads();
    }
}

// ---------------------------------------------------------------------------
// Launch
// ---------------------------------------------------------------------------
extern "C" void kernel_launch(void* const* d_in, const int* in_sizes, int n_in,
                              void* d_out, int out_size) {
    const float* x      = (const float*)d_in[0];
    const int*   mask   = (const int*)  d_in[1];
    const float* alpha1 = (const float*)d_in[2];
    const float* bias1  = (const float*)d_in[3];
    const float* alpha2 = (const float*)d_in[4];
    const float* bias2  = (const float*)d_in[5];
    const float* Wq = (const float*)d_in[6];
    const float* bq = (const float*)d_in[7];
    const float* Wk = (const float*)d_in[8];
    const float* bk = (const float*)d_in[9];
    const float* Wv = (const float*)d_in[10];
    const float* bv = (const float*)d_in[11];
    const float* Wo = (const float*)d_in[12];
    const float* bo = (const float*)d_in[13];
    const float* W1 = (const float*)d_in[14];
    const float* b1 = (const float*)d_in[15];
    const float* W2 = (const float*)d_in[16];
    const float* b2 = (const float*)d_in[17];
    float* out = (float*)d_out;

    __half *x2, *qkvh, *vT, *attn, *h, *wqkvT, *woT, *w1T, *w2T;
    float *xres, *bqkv, *b1p;
    cudaGetSymbolAddress((void**)&x2,    g_x2);
    cudaGetSymbolAddress((void**)&qkvh,  g_qkvh);
    cudaGetSymbolAddress((void**)&vT,    g_vT);
    cudaGetSymbolAddress((void**)&attn,  g_attn);
    cudaGetSymbolAddress((void**)&xres,  g_xres);
    cudaGetSymbolAddress((void**)&h,     g_h);
    cudaGetSymbolAddress((void**)&wqkvT, g_WqkvT);
    cudaGetSymbolAddress((void**)&bqkv,  g_bqkv);
    cudaGetSymbolAddress((void**)&woT,   g_WoT);
    cudaGetSymbolAddress((void**)&w1T,   g_W1T);
    cudaGetSymbolAddress((void**)&b1p,   g_b1p);
    cudaGetSymbolAddress((void**)&w2T,   g_W2T);

    int nsm = 148;
    cudaDeviceGetAttribute(&nsm, cudaDevAttrMultiProcessorCount, 0);

    const int smemG = 3 * (128 * 72 + 256 * 72) * 2;     // 165888
    const int smemF = fl::TOT * 2;                       // 57344
    cudaFuncSetAttribute((const void*)gemm_fp16<1024, 3072, 0, 1, 1, 1>,
        cudaFuncAttributeMaxDynamicSharedMemorySize, smemG);
    cudaFuncSetAttribute((const void*)gemm_fp16<1024, 1024, 0, 0, 0, 0>,
        cudaFuncAttributeMaxDynamicSharedMemorySize, smemG);
    cudaFuncSetAttribute((const void*)gemm_fp16<1024, 512, 1, 0, 1, 0>,
        cudaFuncAttributeMaxDynamicSharedMemorySize, smemG);
    cudaFuncSetAttribute((const void*)gemm_fp16<512, 1024, 0, 0, 0, 0>,
        cudaFuncAttributeMaxDynamicSharedMemorySize, smemG);
    cudaFuncSetAttribute((const void*)flash_kernel,
        cudaFuncAttributeMaxDynamicSharedMemorySize, smemF);

    // 0) prep + batched weight transposes
    prep_kernel<<<(kB * kS * (kS / 32) + 255) / 256, 256>>>(bq, bk, bv, b1, mask);
    transpose_all<<<dim3(32, 32, 6), dim3(32, 8)>>>(Wq, Wk, Wv, Wo, W1, W2);

    // 1) x2 = LN1(x)
    ln_kernel<<<kRows, 256>>>(x, alpha1, bias1, x2);

    // 2) qkv = x2 @ Wqkv + bqkv (q cols pre-scaled 1/8; v cols -> g_vT直接)
    gemm_fp16<1024, 3072, 0, 1, 1, 1><<<dim3(kQKV / 256, kRows / 128), 256, smemG>>>(
        x2, wqkvT, bqkv, nullptr, qkvh);

    // 3) flash attention (persistent, fp16 + ldmatrix)
    flash_kernel<<<2 * nsm, 256, smemF>>>(qkvh, vT, attn);

    // 4) xres = x + attn @ Wo + bo
    gemm_fp16<1024, 1024, 0, 0, 0, 0><<<dim3(kFeat / 256, kRows / 128), 256, smemG>>>(
        attn, woT, bo, x, xres);

    // 5) x2 = LN2(xres)
    ln_kernel<<<kRows, 256>>>(xres, alpha2, bias2, x2);

    // 6) h = ELU(x2 @ W1 + b1)
    gemm_fp16<1024, 512, 1, 0, 1, 0><<<dim3(kFFp / 256, kRows / 128), 256, smemG>>>(
        x2, w1T, b1p, nullptr, h);

    // 7) out = xres + h @ W2 + b2
    gemm_fp16<512, 1024, 0, 0, 0, 0><<<dim3(kFeat / 256, kRows / 128), 256, smemG>>>(
        h, w2T, b2, xres, out);
}